// round 12
// baseline (speedup 1.0000x reference)
#include <cuda_runtime.h>
#include <cuda_bf16.h>
#include <cuda_fp16.h>
#include <cstddef>

#define AN 8192          // sequence length
#define AC 256           // channels
#define AH 4             // heads
#define AD 64            // head dim
#define AC2 512          // 2*C
#define LG2E_D8 0.1803368801111601f   // log2(e)/8

typedef unsigned long long ull;
typedef unsigned int u32;

// ---------------- helpers ----------------
__device__ __forceinline__ float rna_tf32(float x) {
    u32 y;
    asm("cvt.rna.tf32.f32 %0, %1;" : "=r"(y) : "f"(x));
    return __uint_as_float(y);
}
__device__ __forceinline__ u32 smem_u32(const void* p) {
    u32 r;
    asm("{.reg .u64 t; cvta.to.shared.u64 t, %1; cvt.u32.u64 %0, t;}" : "=r"(r) : "l"(p));
    return r;
}
#define CPASYNC16(dst, src) \
    asm volatile("cp.async.cg.shared.global [%0], [%1], 16;" :: "r"(dst), "l"(src))
#define CPASYNC_COMMIT() asm volatile("cp.async.commit_group;" ::: "memory")
#define BAR_SYNC(id) asm volatile("bar.sync %0, 128;" :: "r"(id) : "memory")

// ---------------- mma / ldmatrix ----------------
__device__ __forceinline__ void ldsm_x4(u32 a, u32& r0, u32& r1, u32& r2, u32& r3) {
    asm volatile("ldmatrix.sync.aligned.m8n8.x4.shared.b16 {%0,%1,%2,%3}, [%4];"
                 : "=r"(r0), "=r"(r1), "=r"(r2), "=r"(r3) : "r"(a));
}
__device__ __forceinline__ void ldsm_x4t(u32 a, u32& r0, u32& r1, u32& r2, u32& r3) {
    asm volatile("ldmatrix.sync.aligned.m8n8.x4.trans.shared.b16 {%0,%1,%2,%3}, [%4];"
                 : "=r"(r0), "=r"(r1), "=r"(r2), "=r"(r3) : "r"(a));
}
// f16 inputs, f16 accumulator (2-reg D)
__device__ __forceinline__ void mma_f16a(u32* d, const u32* a, u32 b0, u32 b1) {
    asm volatile(
        "mma.sync.aligned.m16n8k16.row.col.f16.f16.f16.f16 "
        "{%0,%1}, {%2,%3,%4,%5}, {%6,%7}, {%0,%1};"
        : "+r"(d[0]), "+r"(d[1])
        : "r"(a[0]), "r"(a[1]), "r"(a[2]), "r"(a[3]), "r"(b0), "r"(b1));
}
__device__ __forceinline__ void mma_tf32(float* c, const u32* a, u32 b0, u32 b1) {
    asm volatile(
        "mma.sync.aligned.m16n8k8.row.col.f32.tf32.tf32.f32 "
        "{%0,%1,%2,%3}, {%4,%5,%6,%7}, {%8,%9}, {%0,%1,%2,%3};"
        : "+f"(c[0]), "+f"(c[1]), "+f"(c[2]), "+f"(c[3])
        : "r"(a[0]), "r"(a[1]), "r"(a[2]), "r"(a[3]), "r"(b0), "r"(b1));
}
__device__ __forceinline__ u32 ex2h2(u32 s) {
    u32 p;
    asm("ex2.approx.f16x2 %0, %1;" : "=r"(p) : "r"(s));
    return p;
}
__device__ __forceinline__ u32 hadd2(u32 a, u32 b) {
    u32 d;
    asm("add.rn.f16x2 %0, %1, %2;" : "=r"(d) : "r"(a), "r"(b));
    return d;
}
__device__ __forceinline__ void h2f2(u32 h2, float& x, float& y) {
    asm("{\n\t.reg .f16 l, h;\n\tmov.b32 {l, h}, %2;\n\t"
        "cvt.f32.f16 %0, l;\n\tcvt.f32.f16 %1, h;\n\t}"
        : "=f"(x), "=f"(y) : "r"(h2));
}

// ---------------- scratch (allocation-free, device globals) ----------------
__device__ float g_XM[(size_t)AC2 * AN];
__device__ __half g_Qb[(size_t)AH * AN * AD];   // f16, pre-scaled by log2e/8
__device__ __half g_Kb[(size_t)AH * AN * AD];   // f16
__device__ __half g_Vh[(size_t)AH * AN * AD];   // f16 [h][n][d]
__device__ float g_Msg[(size_t)AC * AN];
__device__ float g_Y[(size_t)AC2 * AN];
__device__ float g_Z[(size_t)AC * AN];
#define WOFF_Q 0
#define WOFF_K 65536
#define WOFF_V 131072
#define WOFF_M 196608
#define WOFF_1 262144
#define WOFF_2 524288
#define WTOT   655360
__device__ float g_Wbuf[WTOT];

// ---------------- weight preround to tf32 (rna) ----------------
__global__ __launch_bounds__(256) void preround_w(const float* __restrict__ wq,
                                                  const float* __restrict__ wk,
                                                  const float* __restrict__ wv,
                                                  const float* __restrict__ wm,
                                                  const float* __restrict__ w1,
                                                  const float* __restrict__ w2,
                                                  float* __restrict__ dst) {
    for (int i = blockIdx.x * 256 + threadIdx.x; i < WTOT; i += gridDim.x * 256) {
        float v;
        if (i < WOFF_K) v = wq[i];
        else if (i < WOFF_V) v = wk[i - WOFF_K];
        else if (i < WOFF_M) v = wv[i - WOFF_V];
        else if (i < WOFF_1) v = wm[i - WOFF_M];
        else if (i < WOFF_2) v = w1[i - WOFF_1];
        else v = w2[i - WOFF_2];
        dst[i] = rna_tf32(v);
    }
}

// ---------------- transpose: X[c][n] = rna(descs[n][c]) ----------------
__global__ __launch_bounds__(256) void transpose_in(const float* __restrict__ descs,
                                                    float* __restrict__ X) {
    __shared__ float tile[32][33];
    int n0 = blockIdx.x * 32, c0 = blockIdx.y * 32;
    int tx = threadIdx.x, ty = threadIdx.y;
#pragma unroll
    for (int r = 0; r < 4; r++) {
        int n = n0 + ty + r * 8;
        tile[ty + r * 8][tx] = descs[(size_t)n * AC + c0 + tx];
    }
    __syncthreads();
#pragma unroll
    for (int r = 0; r < 4; r++) {
        int c = c0 + ty + r * 8;
        X[(size_t)c * AN + n0 + tx] = rna_tf32(tile[tx][ty + r * 8]);
    }
}

// ---------------- out[n][c] = descs[n][c] + Z[c][n] ----------------
__global__ __launch_bounds__(256) void transpose_add(const float* __restrict__ descs,
                                                     const float* __restrict__ Z,
                                                     float* __restrict__ out) {
    __shared__ float tile[32][33];
    int n0 = blockIdx.x * 32, c0 = blockIdx.y * 32;
    int tx = threadIdx.x, ty = threadIdx.y;
#pragma unroll
    for (int r = 0; r < 4; r++) {
        int c = c0 + ty + r * 8;
        tile[ty + r * 8][tx] = Z[(size_t)c * AN + n0 + tx];
    }
    __syncthreads();
#pragma unroll
    for (int r = 0; r < 4; r++) {
        int n = n0 + ty + r * 8;
        size_t idx = (size_t)n * AC + c0 + tx;
        out[idx] = descs[idx] + tile[tx][ty + r * 8];
    }
}

// ================= tf32 tensor-core GEMM (proven round-6) =================
#define GA_STRIDE 20
#define GA_BUF (128 * GA_STRIDE)
#define GB_BUF (16 * 128)

struct GemmFrag {
    float acc[4][8][4];
};

__device__ __forceinline__ void gemm_load_stage(const float* __restrict__ A,
                                                const float* __restrict__ B,
                                                int Nn, int K, int m0, int n0,
                                                int tid, int s, int k0,
                                                u32 asb, u32 bsb) {
    u32 ad = asb + (u32)s * (GA_BUF * 4) + (u32)(tid * GA_STRIDE) * 4;
    const float* ag = A + (size_t)(m0 + tid) * K + k0;
#pragma unroll
    for (int j = 0; j < 4; j++) CPASYNC16(ad + j * 16, ag + j * 4);
    int kr = tid >> 3;
    int cb = (tid & 7) * 16;
    u32 bd = bsb + (u32)s * (GB_BUF * 4) + (u32)(kr * 128) * 4;
    const float* bg = B + (size_t)(k0 + kr) * Nn + n0 + cb;
#pragma unroll
    for (int j = 0; j < 4; j++) {
        int pc = (cb + 4 * j) ^ ((kr & 3) << 3);
        CPASYNC16(bd + (u32)pc * 4, bg + 4 * j);
    }
}

__device__ __forceinline__ void gemm_mainloop(const float* __restrict__ A,
                                              const float* __restrict__ B,
                                              int Nn, int K, int m0, int n0,
                                              int tid, int lane, int wm, int wn,
                                              const float* As, const float* Bs,
                                              u32 asb, u32 bsb, GemmFrag& F) {
#pragma unroll
    for (int mt = 0; mt < 4; mt++)
#pragma unroll
        for (int nt = 0; nt < 8; nt++)
#pragma unroll
            for (int e = 0; e < 4; e++) F.acc[mt][nt][e] = 0.f;

    gemm_load_stage(A, B, Nn, K, m0, n0, tid, 0, 0, asb, bsb);
    CPASYNC_COMMIT();

    const int nIter = K >> 4;
    for (int it = 0; it < nIter; it++) {
        if (it + 1 < nIter) {
            gemm_load_stage(A, B, Nn, K, m0, n0, tid, (it + 1) & 1, (it + 1) * 16, asb, bsb);
            CPASYNC_COMMIT();
            asm volatile("cp.async.wait_group 1;" ::: "memory");
        } else {
            asm volatile("cp.async.wait_group 0;" ::: "memory");
        }
        __syncthreads();
        const float* as = As + (it & 1) * GA_BUF;
        const float* bs = Bs + (it & 1) * GB_BUF;
#pragma unroll
        for (int kk = 0; kk < 2; kk++) {
            u32 af[4][4];
            const int c = kk * 8 + (lane & 3);
#pragma unroll
            for (int mt = 0; mt < 4; mt++) {
                int r = wm + mt * 16 + (lane >> 2);
                af[mt][0] = __float_as_uint(as[r * GA_STRIDE + c]);
                af[mt][1] = __float_as_uint(as[(r + 8) * GA_STRIDE + c]);
                af[mt][2] = __float_as_uint(as[r * GA_STRIDE + c + 4]);
                af[mt][3] = __float_as_uint(as[(r + 8) * GA_STRIDE + c + 4]);
            }
#pragma unroll
            for (int nt = 0; nt < 8; nt++) {
                int nb = (wn + nt * 8 + (lane >> 2)) ^ ((lane & 3) << 3);
                u32 b0 = __float_as_uint(bs[c * 128 + nb]);
                u32 b1 = __float_as_uint(bs[(c + 4) * 128 + nb]);
#pragma unroll
                for (int mt = 0; mt < 4; mt++) mma_tf32(F.acc[mt][nt], af[mt], b0, b1);
            }
        }
        __syncthreads();
    }
}

template <int OUTMODE>
__global__ __launch_bounds__(128) void gemm_tc(const float* __restrict__ A,
                                               const float* __restrict__ B,
                                               const float* __restrict__ bias,
                                               float* __restrict__ C,
                                               int M, int Nn, int K) {
    __shared__ __align__(16) float As[2 * GA_BUF];
    __shared__ __align__(16) float Bs[2 * GB_BUF];
    int tid = threadIdx.x, lane = tid & 31, warp = tid >> 5;
    int n0 = blockIdx.x * 128, m0 = blockIdx.y * 128;
    int wm = (warp >> 1) * 64, wn = (warp & 1) * 64;

    GemmFrag F;
    gemm_mainloop(A, B, Nn, K, m0, n0, tid, lane, wm, wn,
                  As, Bs, smem_u32(As), smem_u32(Bs), F);

#pragma unroll
    for (int mt = 0; mt < 4; mt++) {
#pragma unroll
        for (int rr = 0; rr < 2; rr++) {
            int m = m0 + wm + mt * 16 + (lane >> 2) + rr * 8;
            float bv = bias[m];
#pragma unroll
            for (int nt = 0; nt < 8; nt++) {
                float v0 = F.acc[mt][nt][rr * 2 + 0] + bv;
                float v1 = F.acc[mt][nt][rr * 2 + 1] + bv;
                if (OUTMODE == 3) { v0 = rna_tf32(v0); v1 = rna_tf32(v1); }
                int n = n0 + wn + nt * 8 + 2 * (lane & 3);
                float2 st = make_float2(v0, v1);
                *(float2*)&C[(size_t)m * Nn + n] = st;
            }
        }
    }
}

// merged QKV: z=0 Q f16 scaled, z=1 K f16, z=2 V f16 — all [h][n][d]
__global__ __launch_bounds__(128) void qkv_tc(const float* __restrict__ Wbuf,
                                              const float* __restrict__ B,
                                              const float* __restrict__ bq,
                                              const float* __restrict__ bk,
                                              const float* __restrict__ bv,
                                              __half* __restrict__ Qo,
                                              __half* __restrict__ Ko,
                                              __half* __restrict__ Vo) {
    __shared__ __align__(16) float As[2 * GA_BUF];
    __shared__ __align__(16) float Bs[2 * GB_BUF];
    int tid = threadIdx.x, lane = tid & 31, warp = tid >> 5;
    int n0 = blockIdx.x * 128, m0 = blockIdx.y * 128;
    int wm = (warp >> 1) * 64, wn = (warp & 1) * 64;
    int z = blockIdx.z;

    const float* A = Wbuf + (z == 0 ? WOFF_Q : (z == 1 ? WOFF_K : WOFF_V));
    const float* bias = (z == 0 ? bq : (z == 1 ? bk : bv));
    __half* out = (z == 0 ? Qo : (z == 1 ? Ko : Vo));
    float scale = (z == 0) ? LG2E_D8 : 1.f;

    GemmFrag F;
    gemm_mainloop(A, B, AN, AC, m0, n0, tid, lane, wm, wn,
                  As, Bs, smem_u32(As), smem_u32(Bs), F);

#pragma unroll
    for (int mt = 0; mt < 4; mt++) {
#pragma unroll
        for (int rr = 0; rr < 2; rr++) {
            int m = m0 + wm + mt * 16 + (lane >> 2) + rr * 8;
            float bvv = bias[m];
            __half* ob = out + (size_t)(m & 3) * ((size_t)AN * AD) + (m >> 2);
#pragma unroll
            for (int nt = 0; nt < 8; nt++) {
                int n = n0 + wn + nt * 8 + 2 * (lane & 3);
                ob[(size_t)n * AD] = __float2half((F.acc[mt][nt][rr * 2 + 0] + bvv) * scale);
                ob[(size_t)(n + 1) * AD] = __float2half((F.acc[mt][nt][rr * 2 + 1] + bvv) * scale);
            }
        }
    }
}

// ---------------- mma.sync flash attention, split-K dual warp-group ----------------
// 256 threads = 2 groups x 4 warps. 64 queries/block. Group g processes tiles 2j+g.
// QK AND PV both use f16 accumulate (fast path); rowsum kept in f32 per tile.
#define KSTRIDE 72
#define KSTRIDE_B 144
#define TILE_E (64 * KSTRIDE)
#define TILE_B (TILE_E * 2)
#define ATTN_SMEM (TILE_B * 9)   // 82944 bytes

__global__ __launch_bounds__(256, 2) void attn_k(const __half* __restrict__ Qp,
                                                 const __half* __restrict__ Kp,
                                                 const __half* __restrict__ Vp,
                                                 float* __restrict__ Msg) {
    extern __shared__ __align__(16) char dynsm[];
    __half* Qs = (__half*)dynsm;
    __half* Ks = (__half*)(dynsm + TILE_B);
    // V region begins at dynsm + TILE_B * 5

    const int tid = threadIdx.x;
    const int lane = tid & 31, warp = tid >> 5;
    const int group = warp >> 2;           // 0 or 1
    const int wid4 = warp & 3;
    const int gtid = tid & 127;
    const int h = blockIdx.y;
    const int n0 = blockIdx.x * 64;
    const int m0w = wid4 * 16;

    const __half* Qg = Qp + ((size_t)h * AN + n0) * AD;
    const __half* Kg = Kp + (size_t)h * AN * AD;
    const __half* Vg = Vp + (size_t)h * AN * AD;

    u32 qb = smem_u32(Qs);
    u32 kb0 = qb + TILE_B + (u32)group * (2 * TILE_B);
    u32 vb0 = qb + TILE_B * 5 + (u32)group * (2 * TILE_B);

    // ---- prologue: Q (all threads) + this group's tiles j=0, j=1 ----
    {
        int c0 = tid, c1 = tid + 256;
        CPASYNC16(qb + (c0 >> 3) * KSTRIDE_B + (c0 & 7) * 16,
                  Qg + (size_t)(c0 >> 3) * AD + (c0 & 7) * 8);
        CPASYNC16(qb + (c1 >> 3) * KSTRIDE_B + (c1 & 7) * 16,
                  Qg + (size_t)(c1 >> 3) * AD + (c1 & 7) * 8);
        size_t tb = (size_t)(group * 64) * AD;
#pragma unroll
        for (int r = 0; r < 4; r++) {
            int c = gtid + 128 * r;
            u32 so = (c >> 3) * KSTRIDE_B + (c & 7) * 16;
            size_t go = tb + (size_t)(c >> 3) * AD + (c & 7) * 8;
            CPASYNC16(kb0 + so, Kg + go);
            CPASYNC16(vb0 + so, Vg + go);
        }
        CPASYNC_COMMIT();
        tb = (size_t)((2 + group) * 64) * AD;
#pragma unroll
        for (int r = 0; r < 4; r++) {
            int c = gtid + 128 * r;
            u32 so = TILE_B + (c >> 3) * KSTRIDE_B + (c & 7) * 16;
            size_t go = tb + (size_t)(c >> 3) * AD + (c & 7) * 8;
            CPASYNC16(kb0 + so, Kg + go);
            CPASYNC16(vb0 + so, Vg + go);
        }
        CPASYNC_COMMIT();
    }
    asm volatile("cp.async.wait_group 1;" ::: "memory");
    __syncthreads();

    // Q a-fragments
    u32 qa[4][4];
    {
        u32 qaddr = qb + (m0w + (lane & 15)) * KSTRIDE_B + (lane >> 4) * 16;
#pragma unroll
        for (int kk = 0; kk < 4; kk++)
            ldsm_x4(qaddr + kk * 32, qa[kk][0], qa[kk][1], qa[kk][2], qa[kk][3]);
    }

    u32 O2[8][2];   // f16x2 accumulators: O2[t][0]=row r, O2[t][1]=row r+8
#pragma unroll
    for (int t = 0; t < 8; t++) { O2[t][0] = 0u; O2[t][1] = 0u; }
    float rs0 = 0.f, rs1 = 0.f;

    const u32 kfb4 = (lane & 7) * KSTRIDE_B + ((lane >> 3) & 1) * 16 +
                     (lane >> 4) * (8 * KSTRIDE_B);
    const u32 vfb4 = ((lane & 7) + ((lane >> 3) & 1) * 8) * KSTRIDE_B +
                     (lane >> 4) * 16;
    const int barid = group + 1;

    const int nJ = (AN / 64) / 2;   // 64 tiles, 32 per group
    for (int j = 0; j < nJ; j++) {
        u32 kb = kb0 + (u32)(j & 1) * TILE_B;
        u32 vb = vb0 + (u32)(j & 1) * TILE_B;

        // ---- S = Q @ K^T (f16 accumulate; D regs are f16x2 P-layout) ----
        u32 S2[8][2];
#pragma unroll
        for (int t = 0; t < 8; t++) { S2[t][0] = 0u; S2[t][1] = 0u; }
#pragma unroll
        for (int kk = 0; kk < 4; kk++) {
#pragma unroll
            for (int t2 = 0; t2 < 4; t2++) {
                u32 b0, b1, b2, b3;
                ldsm_x4(kb + kfb4 + t2 * (16 * KSTRIDE_B) + kk * 32, b0, b1, b2, b3);
                mma_f16a(S2[2 * t2], qa[kk], b0, b1);
                mma_f16a(S2[2 * t2 + 1], qa[kk], b2, b3);
            }
        }
        // ---- softmax: exp2 directly on f16x2 S ----
        u32 pa[4][4];
#pragma unroll
        for (int t2 = 0; t2 < 4; t2++) {
            pa[t2][0] = ex2h2(S2[2 * t2][0]);
            pa[t2][1] = ex2h2(S2[2 * t2][1]);
            pa[t2][2] = ex2h2(S2[2 * t2 + 1][0]);
            pa[t2][3] = ex2h2(S2[2 * t2 + 1][1]);
        }
        // rowsum via hadd2 tree (f32 accumulate across tiles)
        {
            u32 a0 = hadd2(hadd2(pa[0][0], pa[1][0]), hadd2(pa[2][0], pa[3][0]));
            u32 a2 = hadd2(hadd2(pa[0][2], pa[1][2]), hadd2(pa[2][2], pa[3][2]));
            u32 s0 = hadd2(a0, a2);
            u32 b1 = hadd2(hadd2(pa[0][1], pa[1][1]), hadd2(pa[2][1], pa[3][1]));
            u32 b3 = hadd2(hadd2(pa[0][3], pa[1][3]), hadd2(pa[2][3], pa[3][3]));
            u32 s1 = hadd2(b1, b3);
            float f0, f1, f2, f3;
            h2f2(s0, f0, f1);
            h2f2(s1, f2, f3);
            rs0 += f0 + f1;
            rs1 += f2 + f3;
        }
        // ---- O += P @ V (f16 accumulate) ----
#pragma unroll
        for (int kk2 = 0; kk2 < 4; kk2++) {
#pragma unroll
            for (int t2 = 0; t2 < 4; t2++) {
                u32 b0, b1, b2, b3;
                ldsm_x4t(vb + vfb4 + kk2 * (16 * KSTRIDE_B) + t2 * 32, b0, b1, b2, b3);
                mma_f16a(O2[2 * t2], pa[kk2], b0, b1);
                mma_f16a(O2[2 * t2 + 1], pa[kk2], b2, b3);
            }
        }

        BAR_SYNC(barid);   // group done reading buf (j&1)
        if (j + 2 < nJ) {
            size_t tb = (size_t)((2 * (j + 2) + group) * 64) * AD;
            u32 kbn = kb0 + (u32)(j & 1) * TILE_B;
            u32 vbn = vb0 + (u32)(j & 1) * TILE_B;
#pragma unroll
            for (int r = 0; r < 4; r++) {
                int c = gtid + 128 * r;
                u32 so = (c >> 3) * KSTRIDE_B + (c & 7) * 16;
                size_t go = tb + (size_t)(c >> 3) * AD + (c & 7) * 8;
                CPASYNC16(kbn + so, Kg + go);
                CPASYNC16(vbn + so, Vg + go);
            }
            CPASYNC_COMMIT();
            asm volatile("cp.async.wait_group 1;" ::: "memory");
        } else {
            asm volatile("cp.async.wait_group 0;" ::: "memory");
        }
        BAR_SYNC(barid);   // next buffer visible to group
    }

    // unpack O to f32 for combine/normalize
    float O[8][4];
#pragma unroll
    for (int t = 0; t < 8; t++) {
        h2f2(O2[t][0], O[t][0], O[t][1]);   // row r: cols d0, d0+1
        h2f2(O2[t][1], O[t][2], O[t][3]);   // row r+8
    }

    // ---- combine groups: group1 -> smem -> group0 adds ----
    __syncthreads();
    float* ex = (float*)Ks;   // reuse K region
    if (group == 1) {
        float* s = ex + gtid * 35;
#pragma unroll
        for (int t = 0; t < 8; t++) {
            s[4 * t + 0] = O[t][0]; s[4 * t + 1] = O[t][1];
            s[4 * t + 2] = O[t][2]; s[4 * t + 3] = O[t][3];
        }
        s[32] = rs0;
        s[33] = rs1;
    }
    __syncthreads();
    if (group == 0) {
        const float* s = ex + gtid * 35;
#pragma unroll
        for (int t = 0; t < 8; t++) {
            O[t][0] += s[4 * t + 0]; O[t][1] += s[4 * t + 1];
            O[t][2] += s[4 * t + 2]; O[t][3] += s[4 * t + 3];
        }
        rs0 += s[32];
        rs1 += s[33];

        rs0 += __shfl_xor_sync(0xffffffffu, rs0, 1);
        rs0 += __shfl_xor_sync(0xffffffffu, rs0, 2);
        rs1 += __shfl_xor_sync(0xffffffffu, rs1, 1);
        rs1 += __shfl_xor_sync(0xffffffffu, rs1, 2);
        float inv0 = 1.f / rs0, inv1 = 1.f / rs1;

        int r0 = n0 + m0w + (lane >> 2);
        int r1 = r0 + 8;
        float* mbase = Msg + (size_t)h * AN;
#pragma unroll
        for (int t = 0; t < 8; t++) {
            int d0 = t * 8 + (lane & 3) * 2;
            mbase[(size_t)(4 * d0) * AN + r0] = rna_tf32(O[t][0] * inv0);
            mbase[(size_t)(4 * (d0 + 1)) * AN + r0] = rna_tf32(O[t][1] * inv0);
            mbase[(size_t)(4 * d0) * AN + r1] = rna_tf32(O[t][2] * inv1);
            mbase[(size_t)(4 * (d0 + 1)) * AN + r1] = rna_tf32(O[t][3] * inv1);
        }
    }
}

// ---------------- InstanceNorm (biased var) + ReLU, rounded output ----------------
__global__ __launch_bounds__(256) void inorm_relu(float* __restrict__ Y) {
    const int Nn = AN;
    float* row = Y + (size_t)blockIdx.x * Nn;
    __shared__ float red[256];
    int tid = threadIdx.x;

    float s = 0.f;
    for (int i = tid; i < Nn; i += 256) s += row[i];
    red[tid] = s;
    __syncthreads();
    for (int off = 128; off > 0; off >>= 1) {
        if (tid < off) red[tid] += red[tid + off];
        __syncthreads();
    }
    float mean = red[0] * (1.f / Nn);
    __syncthreads();

    float ss = 0.f;
    for (int i = tid; i < Nn; i += 256) {
        float d = row[i] - mean;
        ss += d * d;
    }
    red[tid] = ss;
    __syncthreads();
    for (int off = 128; off > 0; off >>= 1) {
        if (tid < off) red[tid] += red[tid + off];
        __syncthreads();
    }
    float rstd = rsqrtf(red[0] * (1.f / Nn) + 1e-5f);

    for (int i = tid; i < Nn; i += 256) {
        float v = (row[i] - mean) * rstd;
        row[i] = rna_tf32(v > 0.f ? v : 0.f);
    }
}

// ---------------- launch ----------------
extern "C" void kernel_launch(void* const* d_in, const int* in_sizes, int n_in,
                              void* d_out, int out_size) {
    const float* descs = (const float*)d_in[0];
    const float* Wq = (const float*)d_in[1];
    const float* bq = (const float*)d_in[2];
    const float* Wk = (const float*)d_in[3];
    const float* bk = (const float*)d_in[4];
    const float* Wv = (const float*)d_in[5];
    const float* bv = (const float*)d_in[6];
    const float* Wm = (const float*)d_in[7];
    const float* bm = (const float*)d_in[8];
    const float* W1 = (const float*)d_in[9];
    const float* b1 = (const float*)d_in[10];
    const float* W2 = (const float*)d_in[11];
    const float* b2 = (const float*)d_in[12];
    float* out = (float*)d_out;

    float *xm, *msg, *y, *z, *wbuf;
    __half *qb, *kb, *vh;
    cudaGetSymbolAddress((void**)&xm, g_XM);
    cudaGetSymbolAddress((void**)&qb, g_Qb);
    cudaGetSymbolAddress((void**)&kb, g_Kb);
    cudaGetSymbolAddress((void**)&vh, g_Vh);
    cudaGetSymbolAddress((void**)&msg, g_Msg);
    cudaGetSymbolAddress((void**)&y, g_Y);
    cudaGetSymbolAddress((void**)&z, g_Z);
    cudaGetSymbolAddress((void**)&wbuf, g_Wbuf);

    cudaFuncSetAttribute(attn_k, cudaFuncAttributeMaxDynamicSharedMemorySize, ATTN_SMEM);

    dim3 tb(32, 8);

    preround_w<<<256, 256>>>(Wq, Wk, Wv, Wm, W1, W2, wbuf);
    transpose_in<<<dim3(AN / 32, AC / 32), tb>>>(descs, xm);

    qkv_tc<<<dim3(AN / 128, AC / 128, 3), 128>>>(wbuf, xm, bq, bk, bv, qb, kb, vh);

    attn_k<<<dim3(AN / 64, AH), 256, ATTN_SMEM>>>(qb, kb, vh, msg);

    gemm_tc<3><<<dim3(AN / 128, AC / 128), 128>>>(wbuf + WOFF_M, msg, bm,
                                                  xm + (size_t)AC * AN, AC, AN, AC);
    gemm_tc<0><<<dim3(AN / 128, AC2 / 128), 128>>>(wbuf + WOFF_1, xm, b1, y, AC2, AN, AC2);
    inorm_relu<<<AC2, 256>>>(y);
    gemm_tc<0><<<dim3(AN / 128, AC / 128), 128>>>(wbuf + WOFF_2, y, b2, z, AC, AN, AC2);

    transpose_add<<<dim3(AN / 32, AC / 32), tb>>>(descs, z, out);
}

// round 13
// speedup vs baseline: 1.3163x; 1.3163x over previous
#include <cuda_runtime.h>
#include <cuda_fp16.h>
#include <cstddef>

#define AN 8192          // sequence length
#define AC 256           // channels
#define AH 4             // heads
#define AD 64            // head dim
#define AC2 512          // 2*C
#define LG2E_D8 0.1803368801111601f   // log2(e)/8

typedef unsigned long long ull;
typedef unsigned int u32;

// ---------------- helpers ----------------
__device__ __forceinline__ u32 smem_u32(const void* p) {
    u32 r;
    asm("{.reg .u64 t; cvta.to.shared.u64 t, %1; cvt.u32.u64 %0, t;}" : "=r"(r) : "l"(p));
    return r;
}
#define CPASYNC16(dst, src) \
    asm volatile("cp.async.cg.shared.global [%0], [%1], 16;" :: "r"(dst), "l"(src))
#define CPASYNC_COMMIT() asm volatile("cp.async.commit_group;" ::: "memory")
#define BAR_SYNC(id) asm volatile("bar.sync %0, 128;" :: "r"(id) : "memory")

// ---------------- mma / ldmatrix ----------------
__device__ __forceinline__ void ldsm_x4(u32 a, u32& r0, u32& r1, u32& r2, u32& r3) {
    asm volatile("ldmatrix.sync.aligned.m8n8.x4.shared.b16 {%0,%1,%2,%3}, [%4];"
                 : "=r"(r0), "=r"(r1), "=r"(r2), "=r"(r3) : "r"(a));
}
__device__ __forceinline__ void ldsm_x4t(u32 a, u32& r0, u32& r1, u32& r2, u32& r3) {
    asm volatile("ldmatrix.sync.aligned.m8n8.x4.trans.shared.b16 {%0,%1,%2,%3}, [%4];"
                 : "=r"(r0), "=r"(r1), "=r"(r2), "=r"(r3) : "r"(a));
}
// f16 inputs, f16 accumulator (2-reg D)
__device__ __forceinline__ void mma_f16a(u32* d, const u32* a, u32 b0, u32 b1) {
    asm volatile(
        "mma.sync.aligned.m16n8k16.row.col.f16.f16.f16.f16 "
        "{%0,%1}, {%2,%3,%4,%5}, {%6,%7}, {%0,%1};"
        : "+r"(d[0]), "+r"(d[1])
        : "r"(a[0]), "r"(a[1]), "r"(a[2]), "r"(a[3]), "r"(b0), "r"(b1));
}
// f16 inputs, f32 accumulator
__device__ __forceinline__ void mma_f16(float* c, const u32* a, u32 b0, u32 b1) {
    asm volatile(
        "mma.sync.aligned.m16n8k16.row.col.f32.f16.f16.f32 "
        "{%0,%1,%2,%3}, {%4,%5,%6,%7}, {%8,%9}, {%0,%1,%2,%3};"
        : "+f"(c[0]), "+f"(c[1]), "+f"(c[2]), "+f"(c[3])
        : "r"(a[0]), "r"(a[1]), "r"(a[2]), "r"(a[3]), "r"(b0), "r"(b1));
}
__device__ __forceinline__ u32 ex2h2(u32 s) {
    u32 p;
    asm("ex2.approx.f16x2 %0, %1;" : "=r"(p) : "r"(s));
    return p;
}
__device__ __forceinline__ u32 hadd2(u32 a, u32 b) {
    u32 d;
    asm("add.rn.f16x2 %0, %1, %2;" : "=r"(d) : "r"(a), "r"(b));
    return d;
}
__device__ __forceinline__ void h2f2(u32 h2, float& x, float& y) {
    asm("{\n\t.reg .f16 l, h;\n\tmov.b32 {l, h}, %2;\n\t"
        "cvt.f32.f16 %0, l;\n\tcvt.f32.f16 %1, h;\n\t}"
        : "=f"(x), "=f"(y) : "r"(h2));
}

// ---------------- scratch (allocation-free, device globals) ----------------
__device__ __half g_XMh[(size_t)AC2 * AN];      // rows 0..255: X f16 ; 256..511: Wm@msg f16
__device__ __half g_Qb[(size_t)AH * AN * AD];   // f16, pre-scaled by log2e/8
__device__ __half g_Kb[(size_t)AH * AN * AD];
__device__ __half g_Vh[(size_t)AH * AN * AD];
__device__ __half g_Msgh[(size_t)AC * AN];      // attention out, f16 [c][n]
__device__ float g_Y[(size_t)AC2 * AN];         // W1 out, f32 (for norm stats)
__device__ __half g_Yh[(size_t)AC2 * AN];       // normed+relu, f16
__device__ float g_Z[(size_t)AC * AN];
#define WOFF_Q 0
#define WOFF_K 65536
#define WOFF_V 131072
#define WOFF_M 196608
#define WOFF_1 262144
#define WOFF_2 524288
#define WTOT   655360
__device__ __half g_Wbufh[WTOT];

// ---------------- weight preround to f16 ----------------
__global__ __launch_bounds__(256) void preround_w(const float* __restrict__ wq,
                                                  const float* __restrict__ wk,
                                                  const float* __restrict__ wv,
                                                  const float* __restrict__ wm,
                                                  const float* __restrict__ w1,
                                                  const float* __restrict__ w2,
                                                  __half* __restrict__ dst) {
    for (int i = blockIdx.x * 256 + threadIdx.x; i < WTOT; i += gridDim.x * 256) {
        float v;
        if (i < WOFF_K) v = wq[i];
        else if (i < WOFF_V) v = wk[i - WOFF_K];
        else if (i < WOFF_M) v = wv[i - WOFF_V];
        else if (i < WOFF_1) v = wm[i - WOFF_M];
        else if (i < WOFF_2) v = w1[i - WOFF_1];
        else v = w2[i - WOFF_2];
        dst[i] = __float2half(v);
    }
}

// ---------------- transpose: X[c][n] = f16(descs[n][c]) ----------------
__global__ __launch_bounds__(256) void transpose_in(const float* __restrict__ descs,
                                                    __half* __restrict__ X) {
    __shared__ float tile[32][33];
    int n0 = blockIdx.x * 32, c0 = blockIdx.y * 32;
    int tx = threadIdx.x, ty = threadIdx.y;
#pragma unroll
    for (int r = 0; r < 4; r++) {
        int n = n0 + ty + r * 8;
        tile[ty + r * 8][tx] = descs[(size_t)n * AC + c0 + tx];
    }
    __syncthreads();
#pragma unroll
    for (int r = 0; r < 4; r++) {
        int c = c0 + ty + r * 8;
        X[(size_t)c * AN + n0 + tx] = __float2half(tile[tx][ty + r * 8]);
    }
}

// ---------------- out[n][c] = descs[n][c] + Z[c][n] ----------------
__global__ __launch_bounds__(256) void transpose_add(const float* __restrict__ descs,
                                                     const float* __restrict__ Z,
                                                     float* __restrict__ out) {
    __shared__ float tile[32][33];
    int n0 = blockIdx.x * 32, c0 = blockIdx.y * 32;
    int tx = threadIdx.x, ty = threadIdx.y;
#pragma unroll
    for (int r = 0; r < 4; r++) {
        int c = c0 + ty + r * 8;
        tile[ty + r * 8][tx] = Z[(size_t)c * AN + n0 + tx];
    }
    __syncthreads();
#pragma unroll
    for (int r = 0; r < 4; r++) {
        int n = n0 + ty + r * 8;
        size_t idx = (size_t)n * AC + c0 + tx;
        out[idx] = descs[idx] + tile[tx][ty + r * 8];
    }
}

// ================= f16 tensor-core GEMM =================
// C[M,N] = A[M,K] @ B[K,N] + bias.  Block 128x128, BK=32, 128 threads (4 warps, 64x64 each).
// A smem: [128 m][40 halves] (80B stride).  B smem: [32 k][136 halves] (272B stride).
#define FA_STRIDE_B 80
#define FB_STRIDE_B 272
#define FA_BUF 10240       // 128*80
#define FB_BUF 8704        // 32*272
#define FGEMM_SMEM (2 * FA_BUF + 2 * FB_BUF)

__device__ __forceinline__ void gemm16_load(const __half* __restrict__ A,
                                            const __half* __restrict__ B,
                                            int Nn, int K, int m0, int n0,
                                            int tid, int s, int k0,
                                            u32 asb, u32 bsb) {
#pragma unroll
    for (int r = 0; r < 4; r++) {
        int c = tid + 128 * r;
        int arow = c >> 2, acol = c & 3;
        CPASYNC16(asb + (u32)s * FA_BUF + (u32)(arow * FA_STRIDE_B + acol * 16),
                  A + (size_t)(m0 + arow) * K + k0 + acol * 8);
        int brow = c >> 4, bcol = c & 15;
        CPASYNC16(bsb + (u32)s * FB_BUF + (u32)(brow * FB_STRIDE_B + bcol * 16),
                  B + (size_t)(k0 + brow) * Nn + n0 + bcol * 8);
    }
}

struct FAcc {
    float acc[4][8][4];
};

__device__ __forceinline__ void gemm16_mainloop(const __half* __restrict__ A,
                                                const __half* __restrict__ B,
                                                int Nn, int K, int m0, int n0,
                                                int tid, int lane, int wm, int wn,
                                                u32 asb, u32 bsb, FAcc& F) {
#pragma unroll
    for (int mt = 0; mt < 4; mt++)
#pragma unroll
        for (int nt = 0; nt < 8; nt++)
#pragma unroll
            for (int e = 0; e < 4; e++) F.acc[mt][nt][e] = 0.f;

    gemm16_load(A, B, Nn, K, m0, n0, tid, 0, 0, asb, bsb);
    CPASYNC_COMMIT();

    const u32 afb = (u32)((wm + (lane & 15)) * FA_STRIDE_B + (lane >> 4) * 16);
    const u32 bfb = (u32)(((lane & 7) + ((lane >> 3) & 1) * 8) * FB_STRIDE_B +
                          (lane >> 4) * 16 + wn * 2);

    const int nIter = K >> 5;
    for (int it = 0; it < nIter; it++) {
        if (it + 1 < nIter) {
            gemm16_load(A, B, Nn, K, m0, n0, tid, (it + 1) & 1, (it + 1) * 32, asb, bsb);
            CPASYNC_COMMIT();
            asm volatile("cp.async.wait_group 1;" ::: "memory");
        } else {
            asm volatile("cp.async.wait_group 0;" ::: "memory");
        }
        __syncthreads();
        u32 as = asb + (u32)(it & 1) * FA_BUF;
        u32 bs = bsb + (u32)(it & 1) * FB_BUF;
#pragma unroll
        for (int kk = 0; kk < 2; kk++) {
            u32 af[4][4];
#pragma unroll
            for (int mt = 0; mt < 4; mt++)
                ldsm_x4(as + afb + mt * (16 * FA_STRIDE_B) + kk * 32,
                        af[mt][0], af[mt][1], af[mt][2], af[mt][3]);
#pragma unroll
            for (int nt2 = 0; nt2 < 4; nt2++) {
                u32 b0, b1, b2, b3;
                ldsm_x4t(bs + bfb + kk * (16 * FB_STRIDE_B) + nt2 * 32, b0, b1, b2, b3);
#pragma unroll
                for (int mt = 0; mt < 4; mt++) {
                    mma_f16(F.acc[mt][2 * nt2], af[mt], b0, b1);
                    mma_f16(F.acc[mt][2 * nt2 + 1], af[mt], b2, b3);
                }
            }
        }
        __syncthreads();
    }
}

// OUTMODE 0: float C.  OUTMODE 1: half C.
template <int OUTMODE>
__global__ __launch_bounds__(128) void gemm_f16k(const __half* __restrict__ A,
                                                 const __half* __restrict__ B,
                                                 const float* __restrict__ bias,
                                                 void* __restrict__ Cv,
                                                 int M, int Nn, int K) {
    __shared__ __align__(16) char sm[FGEMM_SMEM];
    u32 asb = smem_u32(sm);
    u32 bsb = asb + 2 * FA_BUF;
    int tid = threadIdx.x, lane = tid & 31, warp = tid >> 5;
    int n0 = blockIdx.x * 128, m0 = blockIdx.y * 128;
    int wm = (warp >> 1) * 64, wn = (warp & 1) * 64;

    FAcc F;
    gemm16_mainloop(A, B, Nn, K, m0, n0, tid, lane, wm, wn, asb, bsb, F);

#pragma unroll
    for (int mt = 0; mt < 4; mt++) {
#pragma unroll
        for (int rr = 0; rr < 2; rr++) {
            int m = m0 + wm + mt * 16 + (lane >> 2) + rr * 8;
            float bv = bias[m];
#pragma unroll
            for (int nt = 0; nt < 8; nt++) {
                float v0 = F.acc[mt][nt][rr * 2 + 0] + bv;
                float v1 = F.acc[mt][nt][rr * 2 + 1] + bv;
                int n = n0 + wn + nt * 8 + 2 * (lane & 3);
                if (OUTMODE == 0) {
                    *(float2*)&((float*)Cv)[(size_t)m * Nn + n] = make_float2(v0, v1);
                } else {
                    *(__half2*)&((__half*)Cv)[(size_t)m * Nn + n] = __floats2half2_rn(v0, v1);
                }
            }
        }
    }
}

// merged QKV: z=0 Q f16 scaled, z=1 K f16, z=2 V f16 — permuted [h][n][d]
__global__ __launch_bounds__(128) void qkv_f16k(const __half* __restrict__ Wbuf,
                                                const __half* __restrict__ B,
                                                const float* __restrict__ bq,
                                                const float* __restrict__ bk,
                                                const float* __restrict__ bv,
                                                __half* __restrict__ Qo,
                                                __half* __restrict__ Ko,
                                                __half* __restrict__ Vo) {
    __shared__ __align__(16) char sm[FGEMM_SMEM];
    u32 asb = smem_u32(sm);
    u32 bsb = asb + 2 * FA_BUF;
    int tid = threadIdx.x, lane = tid & 31, warp = tid >> 5;
    int n0 = blockIdx.x * 128, m0 = blockIdx.y * 128;
    int wm = (warp >> 1) * 64, wn = (warp & 1) * 64;
    int z = blockIdx.z;

    const __half* A = Wbuf + (z == 0 ? WOFF_Q : (z == 1 ? WOFF_K : WOFF_V));
    const float* bias = (z == 0 ? bq : (z == 1 ? bk : bv));
    __half* out = (z == 0 ? Qo : (z == 1 ? Ko : Vo));
    float scale = (z == 0) ? LG2E_D8 : 1.f;

    FAcc F;
    gemm16_mainloop(A, B, AN, AC, m0, n0, tid, lane, wm, wn, asb, bsb, F);

#pragma unroll
    for (int mt = 0; mt < 4; mt++) {
#pragma unroll
        for (int rr = 0; rr < 2; rr++) {
            int m = m0 + wm + mt * 16 + (lane >> 2) + rr * 8;
            float bvv = bias[m];
            __half* ob = out + (size_t)(m & 3) * ((size_t)AN * AD) + (m >> 2);
#pragma unroll
            for (int nt = 0; nt < 8; nt++) {
                int n = n0 + wn + nt * 8 + 2 * (lane & 3);
                ob[(size_t)n * AD] = __float2half((F.acc[mt][nt][rr * 2 + 0] + bvv) * scale);
                ob[(size_t)(n + 1) * AD] = __float2half((F.acc[mt][nt][rr * 2 + 1] + bvv) * scale);
            }
        }
    }
}

// ---------------- mma.sync flash attention (round-11 proven config) ----------------
// QK f16-acc, PV f32-acc. 256 threads = 2 groups x 4 warps, split-K over key tiles.
#define KSTRIDE 72
#define KSTRIDE_B 144
#define TILE_E (64 * KSTRIDE)
#define TILE_B (TILE_E * 2)
#define ATTN_SMEM (TILE_B * 9)   // 82944 bytes

__global__ __launch_bounds__(256, 2) void attn_k(const __half* __restrict__ Qp,
                                                 const __half* __restrict__ Kp,
                                                 const __half* __restrict__ Vp,
                                                 __half* __restrict__ Msg) {
    extern __shared__ __align__(16) char dynsm[];
    __half* Qs = (__half*)dynsm;
    __half* Ks = (__half*)(dynsm + TILE_B);

    const int tid = threadIdx.x;
    const int lane = tid & 31, warp = tid >> 5;
    const int group = warp >> 2;
    const int wid4 = warp & 3;
    const int gtid = tid & 127;
    const int h = blockIdx.y;
    const int n0 = blockIdx.x * 64;
    const int m0w = wid4 * 16;

    const __half* Qg = Qp + ((size_t)h * AN + n0) * AD;
    const __half* Kg = Kp + (size_t)h * AN * AD;
    const __half* Vg = Vp + (size_t)h * AN * AD;

    u32 qb = smem_u32(Qs);
    u32 kb0 = qb + TILE_B + (u32)group * (2 * TILE_B);
    u32 vb0 = qb + TILE_B * 5 + (u32)group * (2 * TILE_B);

    {
        int c0 = tid, c1 = tid + 256;
        CPASYNC16(qb + (c0 >> 3) * KSTRIDE_B + (c0 & 7) * 16,
                  Qg + (size_t)(c0 >> 3) * AD + (c0 & 7) * 8);
        CPASYNC16(qb + (c1 >> 3) * KSTRIDE_B + (c1 & 7) * 16,
                  Qg + (size_t)(c1 >> 3) * AD + (c1 & 7) * 8);
        size_t tb = (size_t)(group * 64) * AD;
#pragma unroll
        for (int r = 0; r < 4; r++) {
            int c = gtid + 128 * r;
            u32 so = (c >> 3) * KSTRIDE_B + (c & 7) * 16;
            size_t go = tb + (size_t)(c >> 3) * AD + (c & 7) * 8;
            CPASYNC16(kb0 + so, Kg + go);
            CPASYNC16(vb0 + so, Vg + go);
        }
        CPASYNC_COMMIT();
        tb = (size_t)((2 + group) * 64) * AD;
#pragma unroll
        for (int r = 0; r < 4; r++) {
            int c = gtid + 128 * r;
            u32 so = TILE_B + (c >> 3) * KSTRIDE_B + (c & 7) * 16;
            size_t go = tb + (size_t)(c >> 3) * AD + (c & 7) * 8;
            CPASYNC16(kb0 + so, Kg + go);
            CPASYNC16(vb0 + so, Vg + go);
        }
        CPASYNC_COMMIT();
    }
    asm volatile("cp.async.wait_group 1;" ::: "memory");
    __syncthreads();

    u32 qa[4][4];
    {
        u32 qaddr = qb + (m0w + (lane & 15)) * KSTRIDE_B + (lane >> 4) * 16;
#pragma unroll
        for (int kk = 0; kk < 4; kk++)
            ldsm_x4(qaddr + kk * 32, qa[kk][0], qa[kk][1], qa[kk][2], qa[kk][3]);
    }

    float O[8][4];
#pragma unroll
    for (int t = 0; t < 8; t++) { O[t][0] = O[t][1] = O[t][2] = O[t][3] = 0.f; }
    float rs0 = 0.f, rs1 = 0.f;

    const u32 kfb4 = (lane & 7) * KSTRIDE_B + ((lane >> 3) & 1) * 16 +
                     (lane >> 4) * (8 * KSTRIDE_B);
    const u32 vfb4 = ((lane & 7) + ((lane >> 3) & 1) * 8) * KSTRIDE_B +
                     (lane >> 4) * 16;
    const int barid = group + 1;

    const int nJ = (AN / 64) / 2;
    for (int j = 0; j < nJ; j++) {
        u32 kb = kb0 + (u32)(j & 1) * TILE_B;
        u32 vb = vb0 + (u32)(j & 1) * TILE_B;

        u32 S2[8][2];
#pragma unroll
        for (int t = 0; t < 8; t++) { S2[t][0] = 0u; S2[t][1] = 0u; }
#pragma unroll
        for (int kk = 0; kk < 4; kk++) {
#pragma unroll
            for (int t2 = 0; t2 < 4; t2++) {
                u32 b0, b1, b2, b3;
                ldsm_x4(kb + kfb4 + t2 * (16 * KSTRIDE_B) + kk * 32, b0, b1, b2, b3);
                mma_f16a(S2[2 * t2], qa[kk], b0, b1);
                mma_f16a(S2[2 * t2 + 1], qa[kk], b2, b3);
            }
        }
        u32 pa[4][4];
#pragma unroll
        for (int t2 = 0; t2 < 4; t2++) {
            pa[t2][0] = ex2h2(S2[2 * t2][0]);
            pa[t2][1] = ex2h2(S2[2 * t2][1]);
            pa[t2][2] = ex2h2(S2[2 * t2 + 1][0]);
            pa[t2][3] = ex2h2(S2[2 * t2 + 1][1]);
        }
        {
            u32 a0 = hadd2(hadd2(pa[0][0], pa[1][0]), hadd2(pa[2][0], pa[3][0]));
            u32 a2 = hadd2(hadd2(pa[0][2], pa[1][2]), hadd2(pa[2][2], pa[3][2]));
            u32 s0 = hadd2(a0, a2);
            u32 b1 = hadd2(hadd2(pa[0][1], pa[1][1]), hadd2(pa[2][1], pa[3][1]));
            u32 b3 = hadd2(hadd2(pa[0][3], pa[1][3]), hadd2(pa[2][3], pa[3][3]));
            u32 s1 = hadd2(b1, b3);
            float f0, f1, f2, f3;
            h2f2(s0, f0, f1);
            h2f2(s1, f2, f3);
            rs0 += f0 + f1;
            rs1 += f2 + f3;
        }
#pragma unroll
        for (int kk2 = 0; kk2 < 4; kk2++) {
#pragma unroll
            for (int t2 = 0; t2 < 4; t2++) {
                u32 b0, b1, b2, b3;
                ldsm_x4t(vb + vfb4 + kk2 * (16 * KSTRIDE_B) + t2 * 32, b0, b1, b2, b3);
                mma_f16(O[2 * t2], pa[kk2], b0, b1);
                mma_f16(O[2 * t2 + 1], pa[kk2], b2, b3);
            }
        }

        BAR_SYNC(barid);
        if (j + 2 < nJ) {
            size_t tb = (size_t)((2 * (j + 2) + group) * 64) * AD;
            u32 kbn = kb0 + (u32)(j & 1) * TILE_B;
            u32 vbn = vb0 + (u32)(j & 1) * TILE_B;
#pragma unroll
            for (int r = 0; r < 4; r++) {
                int c = gtid + 128 * r;
                u32 so = (c >> 3) * KSTRIDE_B + (c & 7) * 16;
                size_t go = tb + (size_t)(c >> 3) * AD + (c & 7) * 8;
                CPASYNC16(kbn + so, Kg + go);
                CPASYNC16(vbn + so, Vg + go);
            }
            CPASYNC_COMMIT();
            asm volatile("cp.async.wait_group 1;" ::: "memory");
        } else {
            asm volatile("cp.async.wait_group 0;" ::: "memory");
        }
        BAR_SYNC(barid);
    }

    __syncthreads();
    float* ex = (float*)Ks;
    if (group == 1) {
        float* s = ex + gtid * 35;
#pragma unroll
        for (int t = 0; t < 8; t++) {
            s[4 * t + 0] = O[t][0]; s[4 * t + 1] = O[t][1];
            s[4 * t + 2] = O[t][2]; s[4 * t + 3] = O[t][3];
        }
        s[32] = rs0;
        s[33] = rs1;
    }
    __syncthreads();
    if (group == 0) {
        const float* s = ex + gtid * 35;
#pragma unroll
        for (int t = 0; t < 8; t++) {
            O[t][0] += s[4 * t + 0]; O[t][1] += s[4 * t + 1];
            O[t][2] += s[4 * t + 2]; O[t][3] += s[4 * t + 3];
        }
        rs0 += s[32];
        rs1 += s[33];

        rs0 += __shfl_xor_sync(0xffffffffu, rs0, 1);
        rs0 += __shfl_xor_sync(0xffffffffu, rs0, 2);
        rs1 += __shfl_xor_sync(0xffffffffu, rs1, 1);
        rs1 += __shfl_xor_sync(0xffffffffu, rs1, 2);
        float inv0 = 1.f / rs0, inv1 = 1.f / rs1;

        int r0 = n0 + m0w + (lane >> 2);
        int r1 = r0 + 8;
        __half* mbase = Msg + (size_t)h * AN;
#pragma unroll
        for (int t = 0; t < 8; t++) {
            int d0 = t * 8 + (lane & 3) * 2;
            mbase[(size_t)(4 * d0) * AN + r0] = __float2half(O[t][0] * inv0);
            mbase[(size_t)(4 * (d0 + 1)) * AN + r0] = __float2half(O[t][1] * inv0);
            mbase[(size_t)(4 * d0) * AN + r1] = __float2half(O[t][2] * inv1);
            mbase[(size_t)(4 * (d0 + 1)) * AN + r1] = __float2half(O[t][3] * inv1);
        }
    }
}

// ---------------- InstanceNorm (biased var) + ReLU: float in, f16 out ----------------
__global__ __launch_bounds__(256) void inorm_relu(const float* __restrict__ Y,
                                                  __half* __restrict__ Yh) {
    const int Nn = AN;
    const float* row = Y + (size_t)blockIdx.x * Nn;
    __half* orow = Yh + (size_t)blockIdx.x * Nn;
    __shared__ float red[256];
    int tid = threadIdx.x;

    float s = 0.f;
    for (int i = tid; i < Nn; i += 256) s += row[i];
    red[tid] = s;
    __syncthreads();
    for (int off = 128; off > 0; off >>= 1) {
        if (tid < off) red[tid] += red[tid + off];
        __syncthreads();
    }
    float mean = red[0] * (1.f / Nn);
    __syncthreads();

    float ss = 0.f;
    for (int i = tid; i < Nn; i += 256) {
        float d = row[i] - mean;
        ss += d * d;
    }
    red[tid] = ss;
    __syncthreads();
    for (int off = 128; off > 0; off >>= 1) {
        if (tid < off) red[tid] += red[tid + off];
        __syncthreads();
    }
    float rstd = rsqrtf(red[0] * (1.f / Nn) + 1e-5f);

    for (int i = tid; i < Nn; i += 256) {
        float v = (row[i] - mean) * rstd;
        orow[i] = __float2half(v > 0.f ? v : 0.f);
    }
}

// ---------------- launch ----------------
extern "C" void kernel_launch(void* const* d_in, const int* in_sizes, int n_in,
                              void* d_out, int out_size) {
    const float* descs = (const float*)d_in[0];
    const float* Wq = (const float*)d_in[1];
    const float* bq = (const float*)d_in[2];
    const float* Wk = (const float*)d_in[3];
    const float* bk = (const float*)d_in[4];
    const float* Wv = (const float*)d_in[5];
    const float* bv = (const float*)d_in[6];
    const float* Wm = (const float*)d_in[7];
    const float* bm = (const float*)d_in[8];
    const float* W1 = (const float*)d_in[9];
    const float* b1 = (const float*)d_in[10];
    const float* W2 = (const float*)d_in[11];
    const float* b2 = (const float*)d_in[12];
    float* out = (float*)d_out;

    __half *xmh, *qb, *kb, *vh, *msgh, *yh, *wbuf;
    float *y, *z;
    cudaGetSymbolAddress((void**)&xmh, g_XMh);
    cudaGetSymbolAddress((void**)&qb, g_Qb);
    cudaGetSymbolAddress((void**)&kb, g_Kb);
    cudaGetSymbolAddress((void**)&vh, g_Vh);
    cudaGetSymbolAddress((void**)&msgh, g_Msgh);
    cudaGetSymbolAddress((void**)&y, g_Y);
    cudaGetSymbolAddress((void**)&yh, g_Yh);
    cudaGetSymbolAddress((void**)&z, g_Z);
    cudaGetSymbolAddress((void**)&wbuf, g_Wbufh);

    cudaFuncSetAttribute(attn_k, cudaFuncAttributeMaxDynamicSharedMemorySize, ATTN_SMEM);

    dim3 tb(32, 8);

    preround_w<<<256, 256>>>(Wq, Wk, Wv, Wm, W1, W2, wbuf);
    transpose_in<<<dim3(AN / 32, AC / 32), tb>>>(descs, xmh);

    qkv_f16k<<<dim3(AN / 128, AC / 128, 3), 128>>>(wbuf, xmh, bq, bk, bv, qb, kb, vh);

    attn_k<<<dim3(AN / 64, AH), 256, ATTN_SMEM>>>(qb, kb, vh, msgh);

    // Wm @ msg -> XMh rows [256,512)  (half out)
    gemm_f16k<1><<<dim3(AN / 128, AC / 128), 128>>>(wbuf + WOFF_M, msgh, bm,
                                                    xmh + (size_t)AC * AN, AC, AN, AC);
    // W1 @ concat -> Y (float out for norm stats)
    gemm_f16k<0><<<dim3(AN / 128, AC2 / 128), 128>>>(wbuf + WOFF_1, xmh, b1, y, AC2, AN, AC2);
    inorm_relu<<<AC2, 256>>>(y, yh);
    // W2 @ Yn -> Z (float)
    gemm_f16k<0><<<dim3(AN / 128, AC / 128), 128>>>(wbuf + WOFF_2, yh, b2, z, AC, AN, AC2);

    transpose_add<<<dim3(AN / 32, AC / 32), tb>>>(descs, z, out);
}